// round 14
// baseline (speedup 1.0000x reference)
#include <cuda_runtime.h>
#include <cuda_bf16.h>
#include <math.h>
#include <stdint.h>

#define NN 100000
#define NE 1600000
#define DD 128
#define NB 391            // ceil(NN/256)
#define BMT 128           // GEMM M tile per CTA

// Scratch (device globals — no allocation allowed)
__device__ float g_rcp[NN];
__device__ float g_sl[NN];
__device__ float g_pre[NN];
__device__ uint32_t g_ah[(size_t)NN * 128];    // A hi: bf16x2, concat [mean|x]
__device__ uint32_t g_al[(size_t)NN * 128];    // A lo
__device__ uint32_t g_bfh[16 * 16 * 2 * 32];   // B hi frags, [ks][ntg][reg][lane]
__device__ uint32_t g_bfl[16 * 16 * 2 * 32];   // B lo frags
__device__ int   g_cnt[NN];
__device__ int   g_off[NN];
__device__ int   g_cur[NN];
__device__ int   g_esrc[NE];
__device__ int   g_partial[512];
__device__ int   g_pinc[512];
__device__ int   g_is64;

// ---- bf16 helpers -----------------------------------------------------------
__device__ __forceinline__ uint32_t bfpack(float a, float b) {
    __nv_bfloat162 t = __floats2bfloat162_rn(a, b);   // .x = a (low 16 bits)
    return *reinterpret_cast<uint32_t*>(&t);
}
__device__ __forceinline__ float bfres(float v) {
    return v - __bfloat162float(__float2bfloat16_rn(v));
}
#define MMA_BF16(d, a0, a1, a2, a3, b0, b1)                                    \
    asm volatile(                                                              \
        "mma.sync.aligned.m16n8k16.row.col.f32.bf16.bf16.f32 "                 \
        "{%0,%1,%2,%3}, {%4,%5,%6,%7}, {%8,%9}, {%0,%1,%2,%3};"                \
        : "+f"(d[0]), "+f"(d[1]), "+f"(d[2]), "+f"(d[3])                       \
        : "r"(a0), "r"(a1), "r"(a2), "r"(a3), "r"(b0), "r"(b1))

// ---------------------------------------------------------------------------
// Detect edge_index dtype (int32 vs int64).
__global__ void detect_kernel(const int* __restrict__ e) {
    if (threadIdx.x == 0) {
        int z = 0;
#pragma unroll
        for (int i = 1; i < 32; i += 2) z |= e[i];
        g_is64 = (z == 0) ? 1 : 0;
    }
}

__global__ void zero_cnt_kernel() {
    int i = blockIdx.x * 256 + threadIdx.x;
    if (i < NN) g_cnt[i] = 0;
}

__global__ void hist_kernel(const int* __restrict__ e32,
                            const long long* __restrict__ e64) {
    unsigned e = blockIdx.x * 256u + threadIdx.x;
    if (e >= NE) return;
    int dst = g_is64 ? (int)__ldg(&e64[NE + e]) : __ldg(&e32[NE + e]);
    atomicAdd(&g_cnt[dst], 1);
}

__global__ void block_sum_kernel() {
    __shared__ int s[256];
    int b = blockIdx.x, t = threadIdx.x;
    int i = b * 256 + t;
    s[t] = (i < NN) ? g_cnt[i] : 0;
    __syncthreads();
#pragma unroll
    for (int off = 128; off > 0; off >>= 1) {
        if (t < off) s[t] += s[t + off];
        __syncthreads();
    }
    if (t == 0) g_partial[b] = s[0];
}

__global__ void scan_partial_kernel() {
    __shared__ int s[512];
    int t = threadIdx.x;
    s[t] = (t < NB) ? g_partial[t] : 0;
    __syncthreads();
#pragma unroll
    for (int off = 1; off < 512; off <<= 1) {
        int v = (t >= off) ? s[t - off] : 0;
        __syncthreads();
        s[t] += v;
        __syncthreads();
    }
    if (t < NB) g_pinc[t] = s[t];
}

__global__ void block_scan_kernel() {
    __shared__ int s[256];
    int b = blockIdx.x, t = threadIdx.x;
    int i = b * 256 + t;
    int c = (i < NN) ? g_cnt[i] : 0;
    s[t] = c;
    __syncthreads();
#pragma unroll
    for (int off = 1; off < 256; off <<= 1) {
        int v = (t >= off) ? s[t - off] : 0;
        __syncthreads();
        s[t] += v;
        __syncthreads();
    }
    if (i < NN) {
        int base = (b > 0) ? g_pinc[b - 1] : 0;
        int excl = base + s[t] - c;
        g_off[i] = excl;
        g_cur[i] = excl;
        g_rcp[i] = 1.f / fmaxf((float)c, 1.f);
    }
}

__global__ void scatter_kernel(const int* __restrict__ e32,
                               const long long* __restrict__ e64) {
    unsigned e = blockIdx.x * 256u + threadIdx.x;
    if (e >= NE) return;
    int src, dst;
    if (g_is64) {
        src = (int)__ldg(&e64[e]);
        dst = (int)__ldg(&e64[NE + e]);
    } else {
        src = __ldg(&e32[e]);
        dst = __ldg(&e32[NE + e]);
    }
    int pos = atomicAdd(&g_cur[dst], 1);
    g_esrc[pos] = src;
}

// B prep: pack concat(w1l,w1r) into per-thread mma fragment order, bf16 hi/lo.
__global__ void prep_bfrag_kernel(const float* __restrict__ w1l,
                                  const float* __restrict__ w1r) {
    int idx = blockIdx.x * 256 + threadIdx.x;      // 0 .. 16383
    if (idx >= 16 * 16 * 2 * 32) return;
    int lane = idx & 31;
    int r    = (idx >> 5) & 1;
    int ntg  = (idx >> 6) & 15;
    int ks   = idx >> 10;
    int k    = ks * 16 + r * 8 + (lane & 3) * 2;
    int n    = ntg * 8 + (lane >> 2);
    float v0 = (k < DD)     ? w1l[n * DD + k]       : w1r[n * DD + k - DD];
    float v1 = (k + 1 < DD) ? w1l[n * DD + k + 1]   : w1r[n * DD + k + 1 - DD];
    g_bfh[idx] = bfpack(v0, v1);
    g_bfl[idx] = bfpack(bfres(v0), bfres(v1));
}

// ---------------------------------------------------------------------------
// Mean aggregation (warp/node) -> bf16 hi/lo A rows; also converts the node's
// own x row into the k>=128 half. One warp per node, lane owns 4 cols.
__global__ void __launch_bounds__(256) agg_kernel(const float* __restrict__ x) {
    unsigned tid  = blockIdx.x * 256u + threadIdx.x;
    unsigned row  = tid >> 5;
    if (row >= NN) return;
    unsigned lane = tid & 31;
    int beg = g_off[row];
    int end = beg + g_cnt[row];
    float4 a0 = make_float4(0.f, 0.f, 0.f, 0.f);
    float4 a1 = make_float4(0.f, 0.f, 0.f, 0.f);
    int e = beg;
    for (; e + 1 < end; e += 2) {
        int s0 = __ldg(&g_esrc[e]);
        int s1 = __ldg(&g_esrc[e + 1]);
        float4 v0 = __ldg((const float4*)(x + (size_t)s0 * DD) + lane);
        float4 v1 = __ldg((const float4*)(x + (size_t)s1 * DD) + lane);
        a0.x += v0.x; a0.y += v0.y; a0.z += v0.z; a0.w += v0.w;
        a1.x += v1.x; a1.y += v1.y; a1.z += v1.z; a1.w += v1.w;
    }
    if (e < end) {
        int s0 = __ldg(&g_esrc[e]);
        float4 v0 = __ldg((const float4*)(x + (size_t)s0 * DD) + lane);
        a0.x += v0.x; a0.y += v0.y; a0.z += v0.z; a0.w += v0.w;
    }
    float r = g_rcp[row];
    float4 m = make_float4((a0.x + a1.x) * r, (a0.y + a1.y) * r,
                           (a0.z + a1.z) * r, (a0.w + a1.w) * r);
    size_t base = (size_t)row * 128 + lane * 2;
    g_ah[base]     = bfpack(m.x, m.y);
    g_ah[base + 1] = bfpack(m.z, m.w);
    g_al[base]     = bfpack(bfres(m.x), bfres(m.y));
    g_al[base + 1] = bfpack(bfres(m.z), bfres(m.w));
    // own x row -> concat cols 128..255 (u32 idx 64..127)
    float4 xv = __ldg((const float4*)(x + (size_t)row * DD) + lane);
    g_ah[base + 64] = bfpack(xv.x, xv.y);
    g_ah[base + 65] = bfpack(xv.z, xv.w);
    g_al[base + 64] = bfpack(bfres(xv.x), bfres(xv.y));
    g_al[base + 65] = bfpack(bfres(xv.z), bfres(xv.w));
}

// ---------------------------------------------------------------------------
// Layer-1 GEMM on tensor cores: pre-split bf16 A (g_ah/g_al), B frags staged
// per k-step in double-buffered smem. 8 warps = 4(M) x 2(N); 3-pass hi/lo.
__global__ void __launch_bounds__(256, 2) sage1_mma_kernel(
    const float* __restrict__ b1l, float* __restrict__ outh) {
    __shared__ __align__(16) uint32_t sbh[2][1024];  // [buf][ntg*2*32 + r*32 + lane]
    __shared__ __align__(16) uint32_t sbl[2][1024];

    const int tid  = threadIdx.x;
    const int w    = tid >> 5;
    const int lane = tid & 31;
    const int gid  = lane >> 2;
    const int tig  = lane & 3;
    const int m0   = blockIdx.x * BMT;

    const int mrow   = m0 + (w & 3) * 32;
    const int ntbase = (w >> 2) * 8;
    const int ncol   = (w >> 2) * 64;

    // A row indices for the two 16-row m-tiles
    const int ra0 = mrow + gid;          // mt=0 rows: ra0, ra0+8
    const int ra1 = mrow + 16 + gid;     // mt=1 rows: ra1, ra1+8
    const size_t rb0 = (size_t)ra0 * 128;
    const size_t rb1 = (size_t)ra1 * 128;

    float acc[2][8][4];
#pragma unroll
    for (int mt = 0; mt < 2; mt++)
#pragma unroll
        for (int nt = 0; nt < 8; nt++)
#pragma unroll
            for (int q = 0; q < 4; q++) acc[mt][nt][q] = 0.f;

    // stage B frags for k-step ks into buffer b (one uint4 per thread per array)
    auto stage = [&](int ks, int b) {
        const uint4* sh = (const uint4*)(g_bfh + ks * 1024);
        const uint4* sl = (const uint4*)(g_bfl + ks * 1024);
        ((uint4*)sbh[b])[tid] = __ldg(sh + tid);
        ((uint4*)sbl[b])[tid] = __ldg(sl + tid);
    };
    // load A frags (hi+lo) for k-step ks
    auto loadA = [&](int ks, uint32_t ah[2][4], uint32_t al[2][4]) {
        size_t o = (size_t)(ks * 8 + tig);
        ah[0][0] = g_ah[rb0 + o];        ah[0][1] = g_ah[rb0 + 1024 + o];
        ah[0][2] = g_ah[rb0 + o + 4];    ah[0][3] = g_ah[rb0 + 1024 + o + 4];
        ah[1][0] = g_ah[rb1 + o];        ah[1][1] = g_ah[rb1 + 1024 + o];
        ah[1][2] = g_ah[rb1 + o + 4];    ah[1][3] = g_ah[rb1 + 1024 + o + 4];
        al[0][0] = g_al[rb0 + o];        al[0][1] = g_al[rb0 + 1024 + o];
        al[0][2] = g_al[rb0 + o + 4];    al[0][3] = g_al[rb0 + 1024 + o + 4];
        al[1][0] = g_al[rb1 + o];        al[1][1] = g_al[rb1 + 1024 + o];
        al[1][2] = g_al[rb1 + o + 4];    al[1][3] = g_al[rb1 + 1024 + o + 4];
    };

    stage(0, 0);
    uint32_t ahc[2][4], alc[2][4];
    loadA(0, ahc, alc);
    __syncthreads();

#pragma unroll 1
    for (int ks = 0; ks < 16; ks++) {
        const int buf = ks & 1;
        uint32_t ahn[2][4], aln[2][4];
        if (ks < 15) {
            stage(ks + 1, buf ^ 1);
            loadA(ks + 1, ahn, aln);
        }

#pragma unroll
        for (int nt = 0; nt < 8; nt++) {
            int fo = (ntbase + nt) * 64 + lane;
            uint32_t bh0 = sbh[buf][fo];
            uint32_t bh1 = sbh[buf][fo + 32];
            uint32_t bl0 = sbl[buf][fo];
            uint32_t bl1 = sbl[buf][fo + 32];
#pragma unroll
            for (int mt = 0; mt < 2; mt++) {
                MMA_BF16(acc[mt][nt], ahc[mt][0], ahc[mt][1], ahc[mt][2],
                         ahc[mt][3], bh0, bh1);
                MMA_BF16(acc[mt][nt], alc[mt][0], alc[mt][1], alc[mt][2],
                         alc[mt][3], bh0, bh1);
                MMA_BF16(acc[mt][nt], ahc[mt][0], ahc[mt][1], ahc[mt][2],
                         ahc[mt][3], bl0, bl1);
            }
        }
        __syncthreads();
        if (ks < 15) {
#pragma unroll
            for (int mt = 0; mt < 2; mt++)
#pragma unroll
                for (int q = 0; q < 4; q++) {
                    ahc[mt][q] = ahn[mt][q];
                    alc[mt][q] = aln[mt][q];
                }
        }
    }

    // Epilogue: + bias, store h (pre-relu).
#pragma unroll
    for (int mt = 0; mt < 2; mt++) {
        int ra = mrow + mt * 16 + gid;
        int rb = ra + 8;
#pragma unroll
        for (int nt = 0; nt < 8; nt++) {
            int col = ncol + nt * 8 + tig * 2;
            float2 bias = *(const float2*)(b1l + col);
            if (ra < NN)
                *(float2*)(outh + (size_t)ra * DD + col) =
                    make_float2(acc[mt][nt][0] + bias.x, acc[mt][nt][1] + bias.y);
            if (rb < NN)
                *(float2*)(outh + (size_t)rb * DD + col) =
                    make_float2(acc[mt][nt][2] + bias.x, acc[mt][nt][3] + bias.y);
        }
    }
}

// ---------------------------------------------------------------------------
// Layer-2 projection: one warp per row.
__global__ void __launch_bounds__(256) proj_kernel(
    const float* __restrict__ outh,
    const float* __restrict__ w2l, const float* __restrict__ b2l,
    const float* __restrict__ w2r) {
    unsigned tid  = blockIdx.x * 256u + threadIdx.x;
    unsigned row  = tid >> 5;
    if (row >= NN) return;
    unsigned lane = tid & 31;
    float4 h  = __ldg((const float4*)(outh + (size_t)row * DD) + lane);
    float4 wl = __ldg((const float4*)w2l + lane);
    float4 wr = __ldg((const float4*)w2r + lane);
    float r0 = fmaxf(h.x, 0.f), r1 = fmaxf(h.y, 0.f);
    float r2 = fmaxf(h.z, 0.f), r3 = fmaxf(h.w, 0.f);
    float sl = r0 * wl.x + r1 * wl.y + r2 * wl.z + r3 * wl.w;
    float sr = r0 * wr.x + r1 * wr.y + r2 * wr.z + r3 * wr.w;
#pragma unroll
    for (int off = 16; off > 0; off >>= 1) {
        sl += __shfl_xor_sync(0xffffffffu, sl, off);
        sr += __shfl_xor_sync(0xffffffffu, sr, off);
    }
    if (lane == 0) { g_sl[row] = sl; g_pre[row] = sr + __ldg(b2l); }
}

// Layer-2 aggregation (CSR gather) + sigmoid, fused.
__global__ void final_kernel(float* __restrict__ out0) {
    int i = blockIdx.x * 256 + threadIdx.x;
    if (i >= NN) return;
    int beg = g_off[i];
    int end = beg + g_cnt[i];
    float t = 0.f;
    for (int e = beg; e < end; e++) t += __ldg(&g_sl[__ldg(&g_esrc[e])]);
    float v = t * g_rcp[i] + g_pre[i];
    out0[i] = 1.f / (1.f + expf(-v));
}

// ---------------------------------------------------------------------------
extern "C" void kernel_launch(void* const* d_in, const int* in_sizes, int n_in,
                              void* d_out, int out_size) {
    const float*     x   = (const float*)d_in[0];
    const int*       e32 = (const int*)d_in[1];
    const long long* e64 = (const long long*)d_in[1];
    const float*     w1l = (const float*)d_in[2];
    const float*     b1l = (const float*)d_in[3];
    const float*     w1r = (const float*)d_in[4];
    const float*     w2l = (const float*)d_in[5];
    const float*     b2l = (const float*)d_in[6];
    const float*     w2r = (const float*)d_in[7];
    float* out0 = (float*)d_out;       // out [N,1]
    float* outh = out0 + NN;           // h   [N,128]

    detect_kernel<<<1, 32>>>(e32);
    zero_cnt_kernel<<<NB, 256>>>();
    hist_kernel<<<(NE + 255) / 256, 256>>>(e32, e64);
    block_sum_kernel<<<NB, 256>>>();
    scan_partial_kernel<<<1, 512>>>();
    block_scan_kernel<<<NB, 256>>>();
    scatter_kernel<<<(NE + 255) / 256, 256>>>(e32, e64);
    prep_bfrag_kernel<<<(16 * 16 * 2 * 32 + 255) / 256, 256>>>(w1l, w1r);
    agg_kernel<<<(NN * 32 + 255) / 256, 256>>>(x);
    sage1_mma_kernel<<<(NN + BMT - 1) / BMT, 256>>>(b1l, outh);
    proj_kernel<<<(NN * 32 + 255) / 256, 256>>>(outh, w2l, b2l, w2r);
    final_kernel<<<(NN + 255) / 256, 256>>>(out0);
}

// round 15
// speedup vs baseline: 1.0107x; 1.0107x over previous
#include <cuda_runtime.h>
#include <cuda_bf16.h>
#include <math.h>
#include <stdint.h>

#define NN 100000
#define NE 1600000
#define DD 128
#define NB 391            // ceil(NN/256)
#define BMT 128           // GEMM M tile per CTA

// Scratch (device globals — no allocation allowed)
__device__ float g_rcp[NN];
__device__ float g_sl[NN];
__device__ float g_pre[NN];
__device__ uint32_t g_ah[(size_t)NN * 128];    // A hi: bf16x2, concat [mean|x]
__device__ uint32_t g_al[(size_t)NN * 128];    // A lo
__device__ uint32_t g_bfh[16 * 16 * 2 * 32];   // B hi frags, [ks][ntg][reg][lane]
__device__ uint32_t g_bfl[16 * 16 * 2 * 32];   // B lo frags
__device__ int   g_cnt[NN];
__device__ int   g_off[NN];
__device__ int   g_cur[NN];
__device__ int   g_esrc[NE];
__device__ int   g_partial[512];
__device__ int   g_pinc[512];
__device__ int   g_is64;

// ---- bf16 helpers -----------------------------------------------------------
__device__ __forceinline__ uint32_t bfpack(float a, float b) {
    __nv_bfloat162 t = __floats2bfloat162_rn(a, b);   // .x = a (low 16 bits)
    return *reinterpret_cast<uint32_t*>(&t);
}
__device__ __forceinline__ float bfres(float v) {
    return v - __bfloat162float(__float2bfloat16_rn(v));
}
#define MMA_BF16(d, a0, a1, a2, a3, b0, b1)                                    \
    asm volatile(                                                              \
        "mma.sync.aligned.m16n8k16.row.col.f32.bf16.bf16.f32 "                 \
        "{%0,%1,%2,%3}, {%4,%5,%6,%7}, {%8,%9}, {%0,%1,%2,%3};"                \
        : "+f"(d[0]), "+f"(d[1]), "+f"(d[2]), "+f"(d[3])                       \
        : "r"(a0), "r"(a1), "r"(a2), "r"(a3), "r"(b0), "r"(b1))

// ---------------------------------------------------------------------------
// Detect edge_index dtype (int32 vs int64).
__global__ void detect_kernel(const int* __restrict__ e) {
    if (threadIdx.x == 0) {
        int z = 0;
#pragma unroll
        for (int i = 1; i < 32; i += 2) z |= e[i];
        g_is64 = (z == 0) ? 1 : 0;
    }
}

__global__ void zero_cnt_kernel() {
    int i = blockIdx.x * 256 + threadIdx.x;
    if (i < NN) g_cnt[i] = 0;
}

__global__ void hist_kernel(const int* __restrict__ e32,
                            const long long* __restrict__ e64) {
    unsigned e = blockIdx.x * 256u + threadIdx.x;
    if (e >= NE) return;
    int dst = g_is64 ? (int)__ldg(&e64[NE + e]) : __ldg(&e32[NE + e]);
    atomicAdd(&g_cnt[dst], 1);
}

__global__ void block_sum_kernel() {
    __shared__ int s[256];
    int b = blockIdx.x, t = threadIdx.x;
    int i = b * 256 + t;
    s[t] = (i < NN) ? g_cnt[i] : 0;
    __syncthreads();
#pragma unroll
    for (int off = 128; off > 0; off >>= 1) {
        if (t < off) s[t] += s[t + off];
        __syncthreads();
    }
    if (t == 0) g_partial[b] = s[0];
}

__global__ void scan_partial_kernel() {
    __shared__ int s[512];
    int t = threadIdx.x;
    s[t] = (t < NB) ? g_partial[t] : 0;
    __syncthreads();
#pragma unroll
    for (int off = 1; off < 512; off <<= 1) {
        int v = (t >= off) ? s[t - off] : 0;
        __syncthreads();
        s[t] += v;
        __syncthreads();
    }
    if (t < NB) g_pinc[t] = s[t];
}

__global__ void block_scan_kernel() {
    __shared__ int s[256];
    int b = blockIdx.x, t = threadIdx.x;
    int i = b * 256 + t;
    int c = (i < NN) ? g_cnt[i] : 0;
    s[t] = c;
    __syncthreads();
#pragma unroll
    for (int off = 1; off < 256; off <<= 1) {
        int v = (t >= off) ? s[t - off] : 0;
        __syncthreads();
        s[t] += v;
        __syncthreads();
    }
    if (i < NN) {
        int base = (b > 0) ? g_pinc[b - 1] : 0;
        int excl = base + s[t] - c;
        g_off[i] = excl;
        g_cur[i] = excl;
        g_rcp[i] = 1.f / fmaxf((float)c, 1.f);
    }
}

__global__ void scatter_kernel(const int* __restrict__ e32,
                               const long long* __restrict__ e64) {
    unsigned e = blockIdx.x * 256u + threadIdx.x;
    if (e >= NE) return;
    int src, dst;
    if (g_is64) {
        src = (int)__ldg(&e64[e]);
        dst = (int)__ldg(&e64[NE + e]);
    } else {
        src = __ldg(&e32[e]);
        dst = __ldg(&e32[NE + e]);
    }
    int pos = atomicAdd(&g_cur[dst], 1);
    g_esrc[pos] = src;
}

// B prep: pack concat(w1l,w1r) into per-thread mma fragment order, bf16 hi/lo.
__global__ void prep_bfrag_kernel(const float* __restrict__ w1l,
                                  const float* __restrict__ w1r) {
    int idx = blockIdx.x * 256 + threadIdx.x;      // 0 .. 16383
    if (idx >= 16 * 16 * 2 * 32) return;
    int lane = idx & 31;
    int r    = (idx >> 5) & 1;
    int ntg  = (idx >> 6) & 15;
    int ks   = idx >> 10;
    int k    = ks * 16 + r * 8 + (lane & 3) * 2;
    int n    = ntg * 8 + (lane >> 2);
    float v0 = (k < DD)     ? w1l[n * DD + k]       : w1r[n * DD + k - DD];
    float v1 = (k + 1 < DD) ? w1l[n * DD + k + 1]   : w1r[n * DD + k + 1 - DD];
    g_bfh[idx] = bfpack(v0, v1);
    g_bfl[idx] = bfpack(bfres(v0), bfres(v1));
}

// ---------------------------------------------------------------------------
// Mean aggregation (warp/node) -> bf16 hi/lo A rows; also converts the node's
// own x row into the k>=128 half. One warp per node, lane owns 4 cols.
__global__ void __launch_bounds__(256) agg_kernel(const float* __restrict__ x) {
    unsigned tid  = blockIdx.x * 256u + threadIdx.x;
    unsigned row  = tid >> 5;
    if (row >= NN) return;
    unsigned lane = tid & 31;
    int beg = g_off[row];
    int end = beg + g_cnt[row];
    float4 a0 = make_float4(0.f, 0.f, 0.f, 0.f);
    float4 a1 = make_float4(0.f, 0.f, 0.f, 0.f);
    int e = beg;
    for (; e + 1 < end; e += 2) {
        int s0 = __ldg(&g_esrc[e]);
        int s1 = __ldg(&g_esrc[e + 1]);
        float4 v0 = __ldg((const float4*)(x + (size_t)s0 * DD) + lane);
        float4 v1 = __ldg((const float4*)(x + (size_t)s1 * DD) + lane);
        a0.x += v0.x; a0.y += v0.y; a0.z += v0.z; a0.w += v0.w;
        a1.x += v1.x; a1.y += v1.y; a1.z += v1.z; a1.w += v1.w;
    }
    if (e < end) {
        int s0 = __ldg(&g_esrc[e]);
        float4 v0 = __ldg((const float4*)(x + (size_t)s0 * DD) + lane);
        a0.x += v0.x; a0.y += v0.y; a0.z += v0.z; a0.w += v0.w;
    }
    float r = g_rcp[row];
    float4 m = make_float4((a0.x + a1.x) * r, (a0.y + a1.y) * r,
                           (a0.z + a1.z) * r, (a0.w + a1.w) * r);
    size_t base = (size_t)row * 128 + lane * 2;
    g_ah[base]     = bfpack(m.x, m.y);
    g_ah[base + 1] = bfpack(m.z, m.w);
    g_al[base]     = bfpack(bfres(m.x), bfres(m.y));
    g_al[base + 1] = bfpack(bfres(m.z), bfres(m.w));
    // own x row -> concat cols 128..255 (u32 idx 64..127)
    float4 xv = __ldg((const float4*)(x + (size_t)row * DD) + lane);
    g_ah[base + 64] = bfpack(xv.x, xv.y);
    g_ah[base + 65] = bfpack(xv.z, xv.w);
    g_al[base + 64] = bfpack(bfres(xv.x), bfres(xv.y));
    g_al[base + 65] = bfpack(bfres(xv.z), bfres(xv.w));
}

// ---------------------------------------------------------------------------
// Layer-1 GEMM on tensor cores: pre-split bf16 A (g_ah/g_al), B frags staged
// per k-step in double-buffered smem. 8 warps = 4(M) x 2(N); 3-pass hi/lo.
__global__ void __launch_bounds__(256, 2) sage1_mma_kernel(
    const float* __restrict__ b1l, float* __restrict__ outh) {
    __shared__ __align__(16) uint32_t sbh[2][1024];  // [buf][ntg*2*32 + r*32 + lane]
    __shared__ __align__(16) uint32_t sbl[2][1024];

    const int tid  = threadIdx.x;
    const int w    = tid >> 5;
    const int lane = tid & 31;
    const int gid  = lane >> 2;
    const int tig  = lane & 3;
    const int m0   = blockIdx.x * BMT;

    const int mrow   = m0 + (w & 3) * 32;
    const int ntbase = (w >> 2) * 8;
    const int ncol   = (w >> 2) * 64;

    // A row indices for the two 16-row m-tiles
    const int ra0 = mrow + gid;          // mt=0 rows: ra0, ra0+8
    const int ra1 = mrow + 16 + gid;     // mt=1 rows: ra1, ra1+8
    const size_t rb0 = (size_t)ra0 * 128;
    const size_t rb1 = (size_t)ra1 * 128;

    float acc[2][8][4];
#pragma unroll
    for (int mt = 0; mt < 2; mt++)
#pragma unroll
        for (int nt = 0; nt < 8; nt++)
#pragma unroll
            for (int q = 0; q < 4; q++) acc[mt][nt][q] = 0.f;

    // stage B frags for k-step ks into buffer b (one uint4 per thread per array)
    auto stage = [&](int ks, int b) {
        const uint4* sh = (const uint4*)(g_bfh + ks * 1024);
        const uint4* sl = (const uint4*)(g_bfl + ks * 1024);
        ((uint4*)sbh[b])[tid] = __ldg(sh + tid);
        ((uint4*)sbl[b])[tid] = __ldg(sl + tid);
    };
    // load A frags (hi+lo) for k-step ks
    auto loadA = [&](int ks, uint32_t ah[2][4], uint32_t al[2][4]) {
        size_t o = (size_t)(ks * 8 + tig);
        ah[0][0] = g_ah[rb0 + o];        ah[0][1] = g_ah[rb0 + 1024 + o];
        ah[0][2] = g_ah[rb0 + o + 4];    ah[0][3] = g_ah[rb0 + 1024 + o + 4];
        ah[1][0] = g_ah[rb1 + o];        ah[1][1] = g_ah[rb1 + 1024 + o];
        ah[1][2] = g_ah[rb1 + o + 4];    ah[1][3] = g_ah[rb1 + 1024 + o + 4];
        al[0][0] = g_al[rb0 + o];        al[0][1] = g_al[rb0 + 1024 + o];
        al[0][2] = g_al[rb0 + o + 4];    al[0][3] = g_al[rb0 + 1024 + o + 4];
        al[1][0] = g_al[rb1 + o];        al[1][1] = g_al[rb1 + 1024 + o];
        al[1][2] = g_al[rb1 + o + 4];    al[1][3] = g_al[rb1 + 1024 + o + 4];
    };

    stage(0, 0);
    uint32_t ahc[2][4], alc[2][4];
    loadA(0, ahc, alc);
    __syncthreads();

#pragma unroll 1
    for (int ks = 0; ks < 16; ks++) {
        const int buf = ks & 1;
        uint32_t ahn[2][4], aln[2][4];
        if (ks < 15) {
            stage(ks + 1, buf ^ 1);
            loadA(ks + 1, ahn, aln);
        }

#pragma unroll
        for (int nt = 0; nt < 8; nt++) {
            int fo = (ntbase + nt) * 64 + lane;
            uint32_t bh0 = sbh[buf][fo];
            uint32_t bh1 = sbh[buf][fo + 32];
            uint32_t bl0 = sbl[buf][fo];
            uint32_t bl1 = sbl[buf][fo + 32];
#pragma unroll
            for (int mt = 0; mt < 2; mt++) {
                MMA_BF16(acc[mt][nt], ahc[mt][0], ahc[mt][1], ahc[mt][2],
                         ahc[mt][3], bh0, bh1);
                MMA_BF16(acc[mt][nt], alc[mt][0], alc[mt][1], alc[mt][2],
                         alc[mt][3], bh0, bh1);
                MMA_BF16(acc[mt][nt], ahc[mt][0], ahc[mt][1], ahc[mt][2],
                         ahc[mt][3], bl0, bl1);
            }
        }
        __syncthreads();
        if (ks < 15) {
#pragma unroll
            for (int mt = 0; mt < 2; mt++)
#pragma unroll
                for (int q = 0; q < 4; q++) {
                    ahc[mt][q] = ahn[mt][q];
                    alc[mt][q] = aln[mt][q];
                }
        }
    }

    // Epilogue: + bias, store h (pre-relu).
#pragma unroll
    for (int mt = 0; mt < 2; mt++) {
        int ra = mrow + mt * 16 + gid;
        int rb = ra + 8;
#pragma unroll
        for (int nt = 0; nt < 8; nt++) {
            int col = ncol + nt * 8 + tig * 2;
            float2 bias = *(const float2*)(b1l + col);
            if (ra < NN)
                *(float2*)(outh + (size_t)ra * DD + col) =
                    make_float2(acc[mt][nt][0] + bias.x, acc[mt][nt][1] + bias.y);
            if (rb < NN)
                *(float2*)(outh + (size_t)rb * DD + col) =
                    make_float2(acc[mt][nt][2] + bias.x, acc[mt][nt][3] + bias.y);
        }
    }
}

// ---------------------------------------------------------------------------
// Layer-2 projection: one warp per row.
__global__ void __launch_bounds__(256) proj_kernel(
    const float* __restrict__ outh,
    const float* __restrict__ w2l, const float* __restrict__ b2l,
    const float* __restrict__ w2r) {
    unsigned tid  = blockIdx.x * 256u + threadIdx.x;
    unsigned row  = tid >> 5;
    if (row >= NN) return;
    unsigned lane = tid & 31;
    float4 h  = __ldg((const float4*)(outh + (size_t)row * DD) + lane);
    float4 wl = __ldg((const float4*)w2l + lane);
    float4 wr = __ldg((const float4*)w2r + lane);
    float r0 = fmaxf(h.x, 0.f), r1 = fmaxf(h.y, 0.f);
    float r2 = fmaxf(h.z, 0.f), r3 = fmaxf(h.w, 0.f);
    float sl = r0 * wl.x + r1 * wl.y + r2 * wl.z + r3 * wl.w;
    float sr = r0 * wr.x + r1 * wr.y + r2 * wr.z + r3 * wr.w;
#pragma unroll
    for (int off = 16; off > 0; off >>= 1) {
        sl += __shfl_xor_sync(0xffffffffu, sl, off);
        sr += __shfl_xor_sync(0xffffffffu, sr, off);
    }
    if (lane == 0) { g_sl[row] = sl; g_pre[row] = sr + __ldg(b2l); }
}

// Layer-2 aggregation (CSR gather) + sigmoid, fused.
__global__ void final_kernel(float* __restrict__ out0) {
    int i = blockIdx.x * 256 + threadIdx.x;
    if (i >= NN) return;
    int beg = g_off[i];
    int end = beg + g_cnt[i];
    float t = 0.f;
    for (int e = beg; e < end; e++) t += __ldg(&g_sl[__ldg(&g_esrc[e])]);
    float v = t * g_rcp[i] + g_pre[i];
    out0[i] = 1.f / (1.f + expf(-v));
}

// ---------------------------------------------------------------------------
extern "C" void kernel_launch(void* const* d_in, const int* in_sizes, int n_in,
                              void* d_out, int out_size) {
    const float*     x   = (const float*)d_in[0];
    const int*       e32 = (const int*)d_in[1];
    const long long* e64 = (const long long*)d_in[1];
    const float*     w1l = (const float*)d_in[2];
    const float*     b1l = (const float*)d_in[3];
    const float*     w1r = (const float*)d_in[4];
    const float*     w2l = (const float*)d_in[5];
    const float*     b2l = (const float*)d_in[6];
    const float*     w2r = (const float*)d_in[7];
    float* out0 = (float*)d_out;       // out [N,1]
    float* outh = out0 + NN;           // h   [N,128]

    detect_kernel<<<1, 32>>>(e32);
    zero_cnt_kernel<<<NB, 256>>>();
    hist_kernel<<<(NE + 255) / 256, 256>>>(e32, e64);
    block_sum_kernel<<<NB, 256>>>();
    scan_partial_kernel<<<1, 512>>>();
    block_scan_kernel<<<NB, 256>>>();
    scatter_kernel<<<(NE + 255) / 256, 256>>>(e32, e64);
    prep_bfrag_kernel<<<(16 * 16 * 2 * 32 + 255) / 256, 256>>>(w1l, w1r);
    agg_kernel<<<(NN * 32 + 255) / 256, 256>>>(x);
    sage1_mma_kernel<<<(NN + BMT - 1) / BMT, 256>>>(b1l, outh);
    proj_kernel<<<(NN * 32 + 255) / 256, 256>>>(outh, w2l, b2l, w2r);
    final_kernel<<<(NN + 255) / 256, 256>>>(out0);
}